// round 1
// baseline (speedup 1.0000x reference)
#include <cuda_runtime.h>
#include <math.h>

#define NU 100000
#define NI 50000
#define DD 64
#define NE 2000000
#define NTOT (NU + NI)
#define GPART 512

// ----------------------------- scratch (static device memory, no allocs) ----
__device__ float g_img_feat[NI * DD];
__device__ float g_txt_feat[NI * DD];
__device__ float g_u_tmp[NU * DD];
__device__ float g_u_acc[NU * DD];
__device__ float g_i_tmp[NI * DD];
__device__ float g_i_acc[NI * DD];

__device__ int   g_cnt_u[NU];
__device__ int   g_offs_u[NU + 1];
__device__ int   g_cur_u[NU];
__device__ int   g_cnt_i[NI];
__device__ int   g_offs_i[NI + 1];
__device__ int   g_cur_i[NI];

__device__ int   g_src_u[NE];
__device__ float g_val_u[NE];
__device__ int   g_src_i[NE];
__device__ float g_val_i[NE];

__device__ float g_part[GPART * DD];
__device__ float g_part1[GPART];
__device__ float g_colmean[DD];
__device__ float g_invrnm;

// ----------------------------- f32x2 packed helpers -------------------------
__device__ __forceinline__ unsigned long long pk2(float x, float y) {
    unsigned long long r;
    asm("mov.b64 %0, {%1, %2};" : "=l"(r) : "f"(x), "f"(y));
    return r;
}
__device__ __forceinline__ void fma2(unsigned long long& d, unsigned long long a,
                                     unsigned long long b) {
    asm("fma.rn.f32x2 %0, %1, %2, %3;" : "=l"(d) : "l"(a), "l"(b), "l"(d));
}
__device__ __forceinline__ float2 upk2(unsigned long long v) {
    float2 f;
    asm("mov.b64 {%0, %1}, %2;" : "=f"(f.x), "=f"(f.y) : "l"(v));
    return f;
}

// ----------------------------- CSR build ------------------------------------
__global__ void k_init() {
    int i = blockIdx.x * blockDim.x + threadIdx.x;
    int st = gridDim.x * blockDim.x;
    for (int k = i; k < NU; k += st) g_cnt_u[k] = 0;
    for (int k = i; k < NI; k += st) g_cnt_i[k] = 0;
}

__global__ void k_hist(const int* __restrict__ eu, const int* __restrict__ ei) {
    int i = blockIdx.x * blockDim.x + threadIdx.x;
    int st = gridDim.x * blockDim.x;
    for (int e = i; e < NE; e += st) {
        atomicAdd(&g_cnt_u[eu[e]], 1);
        atomicAdd(&g_cnt_i[ei[e]], 1);
    }
}

// grid = 2 blocks x 1024 threads: block 0 scans user counts, block 1 item counts
__global__ void k_scan() {
    const int* cnt;
    int* offs;
    int* cur;
    int n;
    if (blockIdx.x == 0) { cnt = g_cnt_u; offs = g_offs_u; cur = g_cur_u; n = NU; }
    else                 { cnt = g_cnt_i; offs = g_offs_i; cur = g_cur_i; n = NI; }

    __shared__ int warpsum[32];
    __shared__ int s_carry;
    int t = threadIdx.x, lane = t & 31, w = t >> 5;
    if (t == 0) { s_carry = 0; offs[0] = 0; }
    __syncthreads();

    for (int base = 0; base < n; base += 1024) {
        int i = base + t;
        int v = (i < n) ? cnt[i] : 0;
        int x = v;
#pragma unroll
        for (int d = 1; d < 32; d <<= 1) {
            int y = __shfl_up_sync(0xffffffffu, x, d);
            if (lane >= d) x += y;
        }
        if (lane == 31) warpsum[w] = x;
        __syncthreads();
        if (w == 0) {
            int ws = warpsum[lane];
#pragma unroll
            for (int d = 1; d < 32; d <<= 1) {
                int y = __shfl_up_sync(0xffffffffu, ws, d);
                if (lane >= d) ws += y;
            }
            warpsum[lane] = ws;
        }
        __syncthreads();
        int inc = x + (w ? warpsum[w - 1] : 0) + s_carry;
        if (i < n) { offs[i + 1] = inc; cur[i] = inc - v; }
        __syncthreads();
        if (t == 1023) s_carry = inc;
        __syncthreads();
    }
}

__global__ void k_scatter(const int* __restrict__ eu, const int* __restrict__ ei,
                          const float* __restrict__ vui, const float* __restrict__ viu) {
    int i = blockIdx.x * blockDim.x + threadIdx.x;
    int st = gridDim.x * blockDim.x;
    for (int e = i; e < NE; e += st) {
        int u = eu[e], it = ei[e];
        int p = atomicAdd(&g_cur_u[u], 1);
        g_src_u[p] = it;
        g_val_u[p] = vui[e];
        int q = atomicAdd(&g_cur_i[it], 1);
        g_src_i[q] = u;
        g_val_i[q] = viu[e];
    }
}

// ----------------------------- dense linear (M x K @ K x 64 + b) ------------
// 32-row tile per block, 256 threads, f32x2 packed FMA; WHICH: 0 -> img, 1 -> txt
template <int K, int WHICH>
__global__ __launch_bounds__(256) void k_linear(const float* __restrict__ A,
                                                const float* __restrict__ W,
                                                const float* __restrict__ bias, int M) {
    __shared__ float sW[64 * 64];
    __shared__ float sA[32 * 68];
    float* out = WHICH ? g_txt_feat : g_img_feat;

    int tid = threadIdx.x;
    int m0 = blockIdx.x * 32;
    int row = tid >> 3, cg = tid & 7;
    unsigned long long acc0 = 0, acc1 = 0, acc2 = 0, acc3 = 0;

    for (int k0 = 0; k0 < K; k0 += 64) {
#pragma unroll
        for (int j = 0; j < 4; j++) {
            int idx = tid + j * 256;
            int r = idx >> 4, c4 = idx & 15;
            *(float4*)&sW[r * 64 + c4 * 4] = *(const float4*)&W[(size_t)(k0 + r) * 64 + c4 * 4];
        }
#pragma unroll
        for (int j = 0; j < 2; j++) {
            int idx = tid + j * 256;
            int r = idx >> 4, c4 = idx & 15;
            int m = m0 + r;
            float4 v = (m < M) ? *(const float4*)&A[(size_t)m * K + k0 + c4 * 4]
                               : make_float4(0.f, 0.f, 0.f, 0.f);
            *(float4*)&sA[r * 68 + c4 * 4] = v;
        }
        __syncthreads();
#pragma unroll 16
        for (int kk = 0; kk < 64; kk++) {
            float a = sA[row * 68 + kk];
            unsigned long long a2 = pk2(a, a);
            ulonglong2 q0 = *(const ulonglong2*)&sW[kk * 64 + cg * 8];
            ulonglong2 q1 = *(const ulonglong2*)&sW[kk * 64 + cg * 8 + 4];
            fma2(acc0, a2, q0.x);
            fma2(acc1, a2, q0.y);
            fma2(acc2, a2, q1.x);
            fma2(acc3, a2, q1.y);
        }
        __syncthreads();
    }

    int m = m0 + row;
    if (m < M) {
        float2 p0 = upk2(acc0), p1 = upk2(acc1), p2 = upk2(acc2), p3 = upk2(acc3);
        int c = cg * 8;
        float* o = &out[(size_t)m * 64 + c];
        o[0] = p0.x + bias[c + 0];
        o[1] = p0.y + bias[c + 1];
        o[2] = p1.x + bias[c + 2];
        o[3] = p1.y + bias[c + 3];
        o[4] = p2.x + bias[c + 4];
        o[5] = p2.y + bias[c + 5];
        o[6] = p3.x + bias[c + 6];
        o[7] = p3.y + bias[c + 7];
    }
}

// ----------------------------- deterministic reductions ---------------------
__global__ __launch_bounds__(256) void k_colsum_part(const float* __restrict__ ue,
                                                     const float* __restrict__ ie) {
    int t = threadIdx.x, col = t & 63, rg = t >> 6;
    float s = 0.f;
    for (int row = blockIdx.x * 4 + rg; row < NTOT; row += GPART * 4) {
        const float* p = (row < NU) ? ue + (size_t)row * 64 : ie + (size_t)(row - NU) * 64;
        s += p[col];
    }
    __shared__ float sm[256];
    sm[t] = s;
    __syncthreads();
    if (t < 64) g_part[blockIdx.x * 64 + t] = sm[t] + sm[t + 64] + sm[t + 128] + sm[t + 192];
}

__global__ void k_colsum_fin() {
    int t = threadIdx.x;  // 64 threads
    float s = 0.f;
    for (int b = 0; b < GPART; b++) s += g_part[b * 64 + t];
    g_colmean[t] = s / (float)NTOT;
}

__global__ __launch_bounds__(256) void k_sumsq_part(const float* __restrict__ ue,
                                                    const float* __restrict__ ie) {
    int t = threadIdx.x, col = t & 63, rg = t >> 6;
    float cm = g_colmean[col];
    float s = 0.f;
    for (int row = blockIdx.x * 4 + rg; row < NTOT; row += GPART * 4) {
        const float* p = (row < NU) ? ue + (size_t)row * 64 : ie + (size_t)(row - NU) * 64;
        float d = p[col] - cm;
        s += d * d;
    }
    __shared__ float sm[256];
    sm[t] = s;
    __syncthreads();
    for (int o = 128; o > 0; o >>= 1) {
        if (t < o) sm[t] += sm[t + o];
        __syncthreads();
    }
    if (t == 0) g_part1[blockIdx.x] = sm[0];
}

__global__ void k_sumsq_fin() {
    float s = 0.f;
    for (int b = 0; b < GPART; b++) s += g_part1[b];
    g_invrnm = 1.0f / sqrtf(s / (float)NTOT + 1e-6f);
}

__global__ void k_normalize(const float* __restrict__ ue, const float* __restrict__ ie) {
    float inv = g_invrnm;
    int st = gridDim.x * blockDim.x;
    int i0 = blockIdx.x * blockDim.x + threadIdx.x;
    const float4* u4 = (const float4*)ue;
    const float4* i4 = (const float4*)ie;
    const float4* cm4 = (const float4*)g_colmean;
    for (int idx = i0; idx < NU * 16; idx += st) {
        float4 v = u4[idx];
        float4 cm = cm4[idx & 15];
        float4 r = make_float4((v.x - cm.x) * inv, (v.y - cm.y) * inv,
                               (v.z - cm.z) * inv, (v.w - cm.w) * inv);
        ((float4*)g_u_acc)[idx] = r;
    }
    for (int idx = i0; idx < NI * 16; idx += st) {
        float4 v = i4[idx];
        float4 cm = cm4[idx & 15];
        float4 r = make_float4((v.x - cm.x) * inv, (v.y - cm.y) * inv,
                               (v.z - cm.z) * inv, (v.w - cm.w) * inv);
        ((float4*)g_i_tmp)[idx] = r;
        ((float4*)g_i_acc)[idx] = r;
    }
}

// ----------------------------- fused dual SpMM (image+text share CSR) -------
// side 0: user-dst CSR, X = g_img_feat/g_txt_feat (Xa_/Xb_ ignored)
// side 1: item-dst CSR, X = Xa_/Xb_ (image_user/text_user in d_out)
__global__ __launch_bounds__(256) void k_spmm_dual(int side, const float* __restrict__ Xa_,
                                                   const float* __restrict__ Xb_,
                                                   float* __restrict__ Ya,
                                                   float* __restrict__ Yb) {
    const int* offs;
    const int* src;
    const float* val;
    const float* Xa;
    const float* Xb;
    int ndst;
    if (side == 0) {
        offs = g_offs_u; src = g_src_u; val = g_val_u; ndst = NU;
        Xa = g_img_feat; Xb = g_txt_feat;
    } else {
        offs = g_offs_i; src = g_src_i; val = g_val_i; ndst = NI;
        Xa = Xa_; Xb = Xb_;
    }
    int w = (blockIdx.x * 256 + threadIdx.x) >> 5;
    if (w >= ndst) return;
    int lane = threadIdx.x & 31;
    int c4 = lane & 15;
    const float4* X = (const float4*)((lane < 16) ? Xa : Xb);
    int s = offs[w], e = offs[w + 1];
    float4 acc = make_float4(0.f, 0.f, 0.f, 0.f);
    int k = s;
    for (; k + 4 <= e; k += 4) {
        int j0 = src[k], j1 = src[k + 1], j2 = src[k + 2], j3 = src[k + 3];
        float v0 = val[k], v1 = val[k + 1], v2 = val[k + 2], v3 = val[k + 3];
        float4 x0 = X[j0 * 16 + c4];
        float4 x1 = X[j1 * 16 + c4];
        float4 x2 = X[j2 * 16 + c4];
        float4 x3 = X[j3 * 16 + c4];
        acc.x += v0 * x0.x; acc.y += v0 * x0.y; acc.z += v0 * x0.z; acc.w += v0 * x0.w;
        acc.x += v1 * x1.x; acc.y += v1 * x1.y; acc.z += v1 * x1.z; acc.w += v1 * x1.w;
        acc.x += v2 * x2.x; acc.y += v2 * x2.y; acc.z += v2 * x2.z; acc.w += v2 * x2.w;
        acc.x += v3 * x3.x; acc.y += v3 * x3.y; acc.z += v3 * x3.z; acc.w += v3 * x3.w;
    }
    for (; k < e; k++) {
        int j = src[k];
        float v = val[k];
        float4 x = X[j * 16 + c4];
        acc.x += v * x.x; acc.y += v * x.y; acc.z += v * x.z; acc.w += v * x.w;
    }
    float4* Y = (float4*)((lane < 16) ? Ya : Yb);
    Y[w * 16 + c4] = acc;
}

// ----------------------------- GNN SpMM with accumulate ---------------------
// side 0: Y=u_tmp <- CSR_u * i_tmp, u_acc += Y  |  side 1: Y=i_tmp <- CSR_i * u_tmp, i_acc += Y
__global__ __launch_bounds__(256) void k_gnn(int side) {
    const int* offs;
    const int* src;
    const float* val;
    const float* X;
    float* Y;
    float* ACC;
    int ndst;
    if (side == 0) {
        offs = g_offs_u; src = g_src_u; val = g_val_u;
        X = g_i_tmp; Y = g_u_tmp; ACC = g_u_acc; ndst = NU;
    } else {
        offs = g_offs_i; src = g_src_i; val = g_val_i;
        X = g_u_tmp; Y = g_i_tmp; ACC = g_i_acc; ndst = NI;
    }
    int w = (blockIdx.x * 256 + threadIdx.x) >> 5;
    if (w >= ndst) return;
    int lane = threadIdx.x & 31;
    const float2* X2 = (const float2*)X;
    int s = offs[w], e = offs[w + 1];
    float2 acc = make_float2(0.f, 0.f);
    int k = s;
    for (; k + 4 <= e; k += 4) {
        int j0 = src[k], j1 = src[k + 1], j2 = src[k + 2], j3 = src[k + 3];
        float v0 = val[k], v1 = val[k + 1], v2 = val[k + 2], v3 = val[k + 3];
        float2 x0 = X2[j0 * 32 + lane];
        float2 x1 = X2[j1 * 32 + lane];
        float2 x2 = X2[j2 * 32 + lane];
        float2 x3 = X2[j3 * 32 + lane];
        acc.x += v0 * x0.x; acc.y += v0 * x0.y;
        acc.x += v1 * x1.x; acc.y += v1 * x1.y;
        acc.x += v2 * x2.x; acc.y += v2 * x2.y;
        acc.x += v3 * x3.x; acc.y += v3 * x3.y;
    }
    for (; k < e; k++) {
        int j = src[k];
        float v = val[k];
        float2 x = X2[j * 32 + lane];
        acc.x += v * x.x; acc.y += v * x.y;
    }
    ((float2*)Y)[w * 32 + lane] = acc;
    float2 a = ((float2*)ACC)[w * 32 + lane];
    a.x += acc.x; a.y += acc.y;
    ((float2*)ACC)[w * 32 + lane] = a;
}

// ----------------------------- final combine --------------------------------
// side 0: users (acc=g_u_acc), side 1: items (acc=g_i_acc)
__global__ __launch_bounds__(256) void k_final(int side, const float* __restrict__ ma,
                                               const float* __restrict__ mb,
                                               float* __restrict__ out) {
    const float* acc = side ? g_i_acc : g_u_acc;
    int n = side ? NI : NU;
    int w = (blockIdx.x * 256 + threadIdx.x) >> 5;
    if (w >= n) return;
    int lane = threadIdx.x & 31;
    float2 a = ((const float2*)ma)[w * 32 + lane];
    float2 b = ((const float2*)mb)[w * 32 + lane];
    float sa = a.x * a.x + a.y * a.y;
    float sb = b.x * b.x + b.y * b.y;
#pragma unroll
    for (int o = 16; o; o >>= 1) {
        sa += __shfl_xor_sync(0xffffffffu, sa, o);
        sb += __shfl_xor_sync(0xffffffffu, sb, o);
    }
    float ia = 0.55f / fmaxf(sqrtf(sa), 1e-12f);
    float ib = 0.55f / fmaxf(sqrtf(sb), 1e-12f);
    float2 g = ((const float2*)acc)[w * 32 + lane];
    float2 o2;
    o2.x = g.x * (1.0f / 3.0f) + a.x * ia + b.x * ib;
    o2.y = g.y * (1.0f / 3.0f) + a.y * ia + b.y * ib;
    ((float2*)out)[w * 32 + lane] = o2;
}

// ----------------------------- launch ---------------------------------------
extern "C" void kernel_launch(void* const* d_in, const int* in_sizes, int n_in,
                              void* d_out, int out_size) {
    const float* image_feats = (const float*)d_in[0];
    const float* text_feats  = (const float*)d_in[1];
    const float* user_emb    = (const float*)d_in[2];
    const float* item_emb    = (const float*)d_in[3];
    const float* W_img       = (const float*)d_in[4];
    const float* b_img       = (const float*)d_in[5];
    const float* W_txt       = (const float*)d_in[6];
    const float* b_txt       = (const float*)d_in[7];
    const float* val_ui      = (const float*)d_in[8];
    const float* val_iu      = (const float*)d_in[9];
    const int*   edge_u      = (const int*)d_in[10];
    const int*   edge_i      = (const int*)d_in[11];

    float* out        = (float*)d_out;
    float* u_out      = out;
    float* i_out      = u_out + (size_t)NU * DD;
    float* image_item = i_out + (size_t)NI * DD;
    float* text_item  = image_item + (size_t)NI * DD;
    float* image_user = text_item + (size_t)NI * DD;
    float* text_user  = image_user + (size_t)NU * DD;

    const int WU = (NU + 7) / 8;  // blocks for warp-per-user-row kernels
    const int WI = (NI + 7) / 8;

    // CSR build
    k_init<<<256, 256>>>();
    k_hist<<<512, 256>>>(edge_u, edge_i);
    k_scan<<<2, 1024>>>();
    k_scatter<<<1024, 256>>>(edge_u, edge_i, val_ui, val_iu);

    // dense projections
    k_linear<1024, 0><<<(NI + 31) / 32, 256>>>(image_feats, W_img, b_img, NI);
    k_linear<384, 1><<<(NI + 31) / 32, 256>>>(text_feats, W_txt, b_txt, NI);

    // normalization statistics (deterministic two-stage)
    k_colsum_part<<<GPART, 256>>>(user_emb, item_emb);
    k_colsum_fin<<<1, 64>>>();
    k_sumsq_part<<<GPART, 256>>>(user_emb, item_emb);
    k_sumsq_fin<<<1, 1>>>();
    k_normalize<<<1024, 256>>>(user_emb, item_emb);

    // modal propagation (fused image+text): user side then item side
    k_spmm_dual<<<WU, 256>>>(0, (const float*)0, (const float*)0, image_user, text_user);
    k_spmm_dual<<<WI, 256>>>(1, image_user, text_user, image_item, text_item);

    // 2-layer GNN with accumulation
    k_gnn<<<WU, 256>>>(0);
    k_gnn<<<WI, 256>>>(1);
    k_gnn<<<WU, 256>>>(0);
    k_gnn<<<WI, 256>>>(1);

    // final combine
    k_final<<<WU, 256>>>(0, image_user, text_user, u_out);
    k_final<<<WI, 256>>>(1, image_item, text_item, i_out);
}